// round 4
// baseline (speedup 1.0000x reference)
#include <cuda_runtime.h>

#define Tn  512
#define Bn  1024
#define Sn  64
#define An  16
#define Hn  128
#define TBn (Tn*Bn)

typedef unsigned long long ull;

__device__ float g_gx[(size_t)TBn * 384];      // x-side gate preactivations [T*B, 3H]
__device__ float g_hidden[(size_t)TBn * Hn];   // GRU hidden states [T*B, H]

// ---------------------------------------------------------------------------
// f32x2 + fast-math helpers
// ---------------------------------------------------------------------------
__device__ __forceinline__ ull pack2(float lo, float hi) {
    ull r;
    asm("mov.b64 %0, {%1, %2};" : "=l"(r)
        : "r"(__float_as_uint(lo)), "r"(__float_as_uint(hi)));
    return r;
}
__device__ __forceinline__ ull dup2(float v) { return pack2(v, v); }
__device__ __forceinline__ void unpack2(ull p, float& lo, float& hi) {
    unsigned int a, b;
    asm("mov.b64 {%0, %1}, %2;" : "=r"(a), "=r"(b) : "l"(p));
    lo = __uint_as_float(a); hi = __uint_as_float(b);
}
__device__ __forceinline__ float hadd2(ull p) {
    float lo, hi; unpack2(p, lo, hi); return lo + hi;
}
__device__ __forceinline__ void fma2(ull& d, ull a, ull b) {
    asm("fma.rn.f32x2 %0, %1, %2, %3;" : "=l"(d) : "l"(a), "l"(b), "l"(d));
}
__device__ __forceinline__ float tanh_fast(float x) {
    float y; asm("tanh.approx.f32 %0, %1;" : "=f"(y) : "f"(x)); return y;
}
__device__ __forceinline__ float sigmoid_fast(float x) {
    return fmaf(0.5f, tanh_fast(0.5f * x), 0.5f);   // 1 MUFU + 1 FMA
}

// ---------------------------------------------------------------------------
// Encoder: fused x -> h1 -> h2 -> gx.  256 threads, 64 rows/block, 2 blk/SM.
// rg = tid>>5 owns rows rg*8..+7 ; cg = tid&31 owns cols {cg+32j, j=0..3}.
// aT[k][row] stride 68 (2x LDS.128 broadcast/k); Wt[k][col] stride 133
// (scalar LDS.32, conflict-free), streamed in 64-k chunks.
// ---------------------------------------------------------------------------
#define EA 68
#define EW 133

__device__ __forceinline__ void gemm64(const float* __restrict__ ap,
                                       const float* __restrict__ wp,
                                       ull acc[4][4])
{
    #pragma unroll 2
    for (int k = 0; k < 64; k++) {
        ulonglong2 aA = *(const ulonglong2*)(ap + k * EA);      // rows (0,1),(2,3)
        ulonglong2 aB = *(const ulonglong2*)(ap + k * EA + 4);  // rows (4,5),(6,7)
        const float* w = wp + k * EW;
        #pragma unroll
        for (int j = 0; j < 4; j++) {
            ull W = dup2(w[32 * j]);
            fma2(acc[0][j], aA.x, W);
            fma2(acc[1][j], aA.y, W);
            fma2(acc[2][j], aB.x, W);
            fma2(acc[3][j], aB.y, W);
        }
    }
}

__device__ __forceinline__ void init_acc4(ull acc[4][4], const float* __restrict__ b,
                                          int cg, int j0)
{
    #pragma unroll
    for (int j = 0; j < 4; j++) {
        ull bb = dup2(b[j0 + cg + 32 * j]);
        #pragma unroll
        for (int p = 0; p < 4; p++) acc[p][j] = bb;
    }
}

__device__ __forceinline__ void store_relu(float* __restrict__ dst,
                                           int cg, int rg, ull acc[4][4])
{
    #pragma unroll
    for (int j = 0; j < 4; j++) {
        int col = cg + 32 * j;
        float v[8];
        unpack2(acc[0][j], v[0], v[1]); unpack2(acc[1][j], v[2], v[3]);
        unpack2(acc[2][j], v[4], v[5]); unpack2(acc[3][j], v[6], v[7]);
        #pragma unroll
        for (int i = 0; i < 8; i++)
            dst[col * EA + rg * 8 + i] = fmaxf(v[i], 0.f);
    }
}

__global__ void __launch_bounds__(256, 2) encoder_kernel(
    const float* __restrict__ x,
    const float* __restrict__ W1, const float* __restrict__ b1,
    const float* __restrict__ W2, const float* __restrict__ b2,
    const float* __restrict__ Wih, const float* __restrict__ bih)
{
    extern __shared__ float sm[];
    float* Wt  = sm;                    // 64*133 = 8512 floats
    float* h1T = sm + 64 * EW;          // 128*68 = 8704
    float* h2T = h1T + 128 * EA;        // 128*68
    float* xT  = h2T;                   // 64*68 aliased (dead after phase A)

    int tid = threadIdx.x;
    int cg  = tid & 31;
    int rg  = tid >> 5;
    int base = blockIdx.x * 64;

    // stage xT + W1 (K=64 fits one chunk)
    for (int idx = tid; idx < 64 * 64; idx += 256) {
        int k = idx & 63, r = idx >> 6;
        xT[k * EA + r] = x[(base + r) * 64 + k];
    }
    for (int idx = tid; idx < 64 * 128; idx += 256) {
        int k = idx & 63, j = idx >> 6;
        Wt[k * EW + j] = W1[j * 64 + k];
    }
    __syncthreads();

    ull acc[4][4];

    // ---- Phase A: h1 = relu(x @ W1^T + b1) ----
    init_acc4(acc, b1, cg, 0);
    gemm64(xT + rg * 8, Wt + cg, acc);
    store_relu(h1T, cg, rg, acc);

    // ---- Phase B: h2 = relu(h1 @ W2^T + b2), K=128 in 2 chunks ----
    init_acc4(acc, b2, cg, 0);
    #pragma unroll 1
    for (int h = 0; h < 2; h++) {
        __syncthreads();   // h1T visible / previous Wt reads done
        for (int idx = tid; idx < 64 * 128; idx += 256) {
            int kl = idx & 63, j = idx >> 6;
            Wt[kl * EW + j] = W2[j * 128 + h * 64 + kl];
        }
        __syncthreads();
        gemm64(h1T + (h * 64) * EA + rg * 8, Wt + cg, acc);
    }
    __syncthreads();       // gemm reads done before h2T overwrite (aliases xT only, safe) and Wt restage
    store_relu(h2T, cg, rg, acc);

    // ---- Phase C: gx = h2 @ Wih^T + bih, 3 col passes x 2 k chunks ----
    #pragma unroll 1
    for (int pp = 0; pp < 3; pp++) {
        init_acc4(acc, bih, cg, pp * 128);
        #pragma unroll 1
        for (int h = 0; h < 2; h++) {
            __syncthreads();   // h2T visible (first iter) / prior Wt reads done
            for (int idx = tid; idx < 64 * 128; idx += 256) {
                int kl = idx & 63, j = idx >> 6;
                Wt[kl * EW + j] = Wih[(pp * 128 + j) * 128 + h * 64 + kl];
            }
            __syncthreads();
            gemm64(h2T + (h * 64) * EA + rg * 8, Wt + cg, acc);
        }
        // store to g_gx (coalesced scalar stores)
        #pragma unroll
        for (int j = 0; j < 4; j++) {
            int col = pp * 128 + cg + 32 * j;
            #pragma unroll
            for (int p = 0; p < 4; p++) {
                float va, vb;
                unpack2(acc[p][j], va, vb);
                size_t row0 = (size_t)(base + rg * 8 + 2 * p);
                g_gx[row0 * 384 + col]       = va;
                g_gx[(row0 + 1) * 384 + col] = vb;
            }
        }
    }
}

// ---------------------------------------------------------------------------
// GRU scan: 128 blocks x 8 batch rows, 256 threads.
// kh = tid>>7 picks k-half (0..63 / 64..127); c = tid&127 is the column.
// Partial sums reduced through smem once per step; kh=0 does the epilogue.
// Whh gate-major in smem [g][c][k] stride 132; h double-buffered [r][k] str 132.
// ---------------------------------------------------------------------------
#define WS 132

__global__ void __launch_bounds__(256, 1) scan_kernel(
    const float* __restrict__ done, const float* __restrict__ gru0,
    const float* __restrict__ Whh, const float* __restrict__ bhh,
    float* __restrict__ out)
{
    extern __shared__ float sm[];
    float* wsm = sm;                       // 3*128*132 = 50688 floats
    float* hb  = wsm + 3 * 128 * WS;       // 2*8*132   = 2112
    float* red = hb + 2 * 8 * WS;          // 128*25    = 3200   (total 224000 B)

    int tid = threadIdx.x;
    int c   = tid & 127;
    int kh  = tid >> 7;
    int b0  = blockIdx.x << 3;

    for (int idx = tid; idx < 384 * 128; idx += 256) {
        int k = idx & 127, j = idx >> 7;
        int g = j >> 7, cc = j & 127;
        wsm[g * 128 * WS + cc * WS + k] = Whh[j * 128 + k];
    }
    for (int idx = tid; idx < 8 * 128; idx += 256) {
        int r = idx >> 7, cc = idx & 127;
        hb[r * WS + cc] = gru0[(b0 + r) * 128 + cc] * (1.f - done[b0 + r]);
    }
    __syncthreads();

    const float* wp0 = wsm + c * WS + kh * 64;
    const float* wp1 = wsm + 128 * WS + c * WS + kh * 64;
    const float* wp2 = wsm + 256 * WS + c * WS + kh * 64;

    float br = bhh[c], bz = bhh[c + 128], bn = bhh[c + 256];

    float gx0[8], gx1[8], gx2[8];
    if (kh == 0) {
        #pragma unroll
        for (int r = 0; r < 8; r++) {
            size_t row = (size_t)(b0 + r);
            gx0[r] = g_gx[row * 384 + c];
            gx1[r] = g_gx[row * 384 + 128 + c];
            gx2[r] = g_gx[row * 384 + 256 + c];
        }
    }

    int cur = 0;
    for (int t = 0; t < Tn; t++) {
        // prefetch next step's gx + done (kh=0 only; hidden under k-loop)
        float gn0[8], gn1[8], gn2[8], dn[8];
        if (kh == 0) {
            int tnx = (t + 1 < Tn) ? (t + 1) : t;
            #pragma unroll
            for (int r = 0; r < 8; r++) {
                size_t row = (size_t)tnx * Bn + b0 + r;
                gn0[r] = g_gx[row * 384 + c];
                gn1[r] = g_gx[row * 384 + 128 + c];
                gn2[r] = g_gx[row * 384 + 256 + c];
                dn[r] = (t + 1 < Tn) ? done[(size_t)(t + 1) * Bn + b0 + r] : 0.f;
            }
        }

        const float* hbc = hb + cur * (8 * WS) + kh * 64;
        ull aR[8], aZ[8], aN[8];
        #pragma unroll
        for (int r = 0; r < 8; r++) { aR[r] = 0ull; aZ[r] = 0ull; aN[r] = 0ull; }

        #pragma unroll 2
        for (int k4 = 0; k4 < 16; k4++) {
            int k = k4 * 4;
            ulonglong2 wr = *(const ulonglong2*)(wp0 + k);
            ulonglong2 wz = *(const ulonglong2*)(wp1 + k);
            ulonglong2 wn = *(const ulonglong2*)(wp2 + k);
            #pragma unroll
            for (int r = 0; r < 8; r++) {
                ulonglong2 hp = *(const ulonglong2*)(hbc + r * WS + k);  // broadcast
                fma2(aR[r], hp.x, wr.x); fma2(aR[r], hp.y, wr.y);
                fma2(aZ[r], hp.x, wz.x); fma2(aZ[r], hp.y, wz.y);
                fma2(aN[r], hp.x, wn.x); fma2(aN[r], hp.y, wn.y);
            }
        }

        if (kh == 1) {
            #pragma unroll
            for (int r = 0; r < 8; r++) {
                red[c * 25 + r]      = hadd2(aR[r]);
                red[c * 25 + 8 + r]  = hadd2(aZ[r]);
                red[c * 25 + 16 + r] = hadd2(aN[r]);
            }
        }
        __syncthreads();

        if (kh == 0) {
            const float* hfull = hb + cur * (8 * WS);
            float* hnxt = hb + (cur ^ 1) * (8 * WS);
            #pragma unroll
            for (int r = 0; r < 8; r++) {
                float sr = hadd2(aR[r]) + red[c * 25 + r]      + br + gx0[r];
                float sz = hadd2(aZ[r]) + red[c * 25 + 8 + r]  + bz + gx1[r];
                float sn = hadd2(aN[r]) + red[c * 25 + 16 + r] + bn;
                float rg_ = sigmoid_fast(sr);
                float zg  = sigmoid_fast(sz);
                float ng  = tanh_fast(gx2[r] + rg_ * sn);
                float hold = hfull[r * WS + c];
                float hnew = (1.f - zg) * ng + zg * hold;
                g_hidden[((size_t)t * Bn + b0 + r) * Hn + c] = hnew;
                hnxt[r * WS + c] = hnew * (1.f - dn[r]);
                if (t == Tn - 1)
                    out[(size_t)TBn * 3 + (b0 + r) * Hn + c] = hnew;
                gx0[r] = gn0[r]; gx1[r] = gn1[r]; gx2[r] = gn2[r];
            }
        }
        __syncthreads();
        cur ^= 1;
    }
}

// ---------------------------------------------------------------------------
// Heads: 256 rows/block, thread-per-row.
// ---------------------------------------------------------------------------
__global__ void __launch_bounds__(256, 1) heads_kernel(
    const int* __restrict__ action,
    const float* __restrict__ Wa, const float* __restrict__ ba,
    const float* __restrict__ Wc, const float* __restrict__ bc,
    float* __restrict__ out)
{
    extern __shared__ float sm[];
    const int OFF_WA = 256 * 129;
    const int OFF_WC = OFF_WA + 16 * 128;
    int tid  = threadIdx.x;
    int base = blockIdx.x << 8;

    for (int idx = tid; idx < 256 * 128; idx += 256) {
        int r = idx >> 7, k = idx & 127;
        sm[r * 129 + k] = g_hidden[(size_t)(base + r) * 128 + k];
    }
    for (int idx = tid; idx < 16 * 128; idx += 256) sm[OFF_WA + idx] = Wa[idx];
    if (tid < 128) sm[OFF_WC + tid] = Wc[tid];
    __syncthreads();

    float l[16];
    #pragma unroll
    for (int j = 0; j < 16; j++) l[j] = ba[j];
    float v = bc[0];
    const float* hrow = &sm[tid * 129];
    #pragma unroll 4
    for (int k = 0; k < 128; k++) {
        float hv = hrow[k];
        #pragma unroll
        for (int j = 0; j < 16; j++) l[j] += sm[OFF_WA + j * 128 + k] * hv;
        v += sm[OFF_WC + k] * hv;
    }
    float mx = l[0];
    #pragma unroll
    for (int j = 1; j < 16; j++) mx = fmaxf(mx, l[j]);
    float se = 0.f, pl = 0.f;
    #pragma unroll
    for (int j = 0; j < 16; j++) {
        float e = __expf(l[j] - mx);
        se += e; pl += e * l[j];
    }
    float lse = mx + __logf(se);
    int row = base + tid;
    int a = action[row];
    float la = 0.f;
    #pragma unroll
    for (int j = 0; j < 16; j++) la = (a == j) ? l[j] : la;
    out[(size_t)row * 3 + 0] = la - lse;
    out[(size_t)row * 3 + 1] = lse - pl / se;
    out[(size_t)row * 3 + 2] = v;
}

// ---------------------------------------------------------------------------
extern "C" void kernel_launch(void* const* d_in, const int* in_sizes, int n_in,
                              void* d_out, int out_size)
{
    const float* x    = (const float*)d_in[0];
    const float* done = (const float*)d_in[1];
    const int*   act  = (const int*)  d_in[2];
    const float* gru  = (const float*)d_in[3];
    const float* W1   = (const float*)d_in[4];
    const float* b1   = (const float*)d_in[5];
    const float* W2   = (const float*)d_in[6];
    const float* b2   = (const float*)d_in[7];
    const float* Wih  = (const float*)d_in[8];
    const float* bih  = (const float*)d_in[9];
    const float* Whh  = (const float*)d_in[10];
    const float* bhh  = (const float*)d_in[11];
    const float* Wa   = (const float*)d_in[12];
    const float* ba   = (const float*)d_in[13];
    const float* Wc   = (const float*)d_in[14];
    const float* bc   = (const float*)d_in[15];
    float* out = (float*)d_out;

    size_t enc_smem  = (size_t)(64 * EW + 2 * 128 * EA) * sizeof(float);          // 103680 B
    size_t scan_smem = (size_t)(3 * 128 * WS + 2 * 8 * WS + 128 * 25) * sizeof(float); // 224000 B
    size_t head_smem = (size_t)(256 * 129 + 16 * 128 + 128) * sizeof(float);      // 140800 B

    cudaFuncSetAttribute(encoder_kernel, cudaFuncAttributeMaxDynamicSharedMemorySize, (int)enc_smem);
    cudaFuncSetAttribute(scan_kernel,    cudaFuncAttributeMaxDynamicSharedMemorySize, (int)scan_smem);
    cudaFuncSetAttribute(heads_kernel,   cudaFuncAttributeMaxDynamicSharedMemorySize, (int)head_smem);

    encoder_kernel<<<TBn / 64, 256, enc_smem>>>(x, W1, b1, W2, b2, Wih, bih);
    scan_kernel<<<128, 256, scan_smem>>>(done, gru, Whh, bhh, out);
    heads_kernel<<<TBn / 256, 256, head_smem>>>(act, Wa, ba, Wc, bc, out);
}